// round 15
// baseline (speedup 1.0000x reference)
#include <cuda_runtime.h>
#include <cuda_bf16.h>
#include <math.h>
#include <stdint.h>

#define LATENT 256
#define HID 512
#define NT 16
#define MAXB 2048
#define K1E (3 * LATENT)   // 768
#define K2E (3 * HID)      // 1536

// scratch (allocation-free rule: device globals)
__device__ float g_h[MAXB * HID];
__device__ float g_p[MAXB];
__device__ __nv_bfloat16 g_zx[MAXB * K1E];
__device__ __nv_bfloat16 g_hx[(size_t)MAXB * K2E];
__device__ __nv_bfloat16 g_w1[K1E * HID];   // [kE][n], blocks [hi|hi|lo]
__device__ __nv_bfloat16 g_w2[K2E * HID];

// ---------------- helpers ---------------------------------------------------
__device__ __forceinline__ uint32_t smem_u32(const void* p) {
    uint32_t a;
    asm("{ .reg .u64 t; cvta.to.shared.u64 t, %1; cvt.u32.u64 %0, t; }"
        : "=r"(a) : "l"(p));
    return a;
}
__device__ __forceinline__ void ldm_x4(uint32_t* r, uint32_t addr) {
    asm volatile("ldmatrix.sync.aligned.m8n8.x4.shared.b16 {%0,%1,%2,%3}, [%4];"
        : "=r"(r[0]), "=r"(r[1]), "=r"(r[2]), "=r"(r[3]) : "r"(addr));
}
__device__ __forceinline__ void ldm_x4_t(uint32_t* r, uint32_t addr) {
    asm volatile("ldmatrix.sync.aligned.m8n8.x4.trans.shared.b16 {%0,%1,%2,%3}, [%4];"
        : "=r"(r[0]), "=r"(r[1]), "=r"(r[2]), "=r"(r[3]) : "r"(addr));
}
__device__ __forceinline__ void mma16816(float* c, const uint32_t* a, const uint32_t* b) {
    asm volatile(
        "mma.sync.aligned.m16n8k16.row.col.f32.bf16.bf16.f32 "
        "{%0,%1,%2,%3}, {%4,%5,%6,%7}, {%8,%9}, {%0,%1,%2,%3};"
        : "+f"(c[0]), "+f"(c[1]), "+f"(c[2]), "+f"(c[3])
        : "r"(a[0]), "r"(a[1]), "r"(a[2]), "r"(a[3]), "r"(b[0]), "r"(b[1]));
}
__device__ __forceinline__ void bfsplit(float x, __nv_bfloat16& hi, __nv_bfloat16& lo) {
    hi = __float2bfloat16(x);
    lo = __float2bfloat16(x - __bfloat162float(hi));
}

// ---------------- prep kernels ----------------------------------------------
// z [Bsz,256] -> zx [Bsz, 768] = [hi | lo | hi]; also zero g_p.
__global__ __launch_bounds__(256)
void prep_z(const float* __restrict__ z, __nv_bfloat16* __restrict__ zx,
            float* __restrict__ gp, int Bsz)
{
    int i = blockIdx.x * 256 + threadIdx.x;     // float2 index
    if (i < Bsz) gp[i] = 0.f;
    if (i >= Bsz * (LATENT / 2)) return;
    int row = i / (LATENT / 2), k2 = i - row * (LATENT / 2);
    float2 v = reinterpret_cast<const float2*>(z)[i];
    __nv_bfloat16 h0, l0, h1, l1;
    bfsplit(v.x, h0, l0); bfsplit(v.y, h1, l1);
    __nv_bfloat16* o = zx + (size_t)row * K1E + k2 * 2;
    *reinterpret_cast<__nv_bfloat162*>(o)              = __halves2bfloat162(h0, h1);
    *reinterpret_cast<__nv_bfloat162*>(o + LATENT)     = __halves2bfloat162(l0, l1);
    *reinterpret_cast<__nv_bfloat162*>(o + 2 * LATENT) = __halves2bfloat162(h0, h1);
}

// W_z [256,512] -> w1 [768,512] = row-blocks [hi | hi | lo]  (linear copy)
__global__ __launch_bounds__(256)
void prep_w1(const float* __restrict__ W, __nv_bfloat16* __restrict__ o)
{
    int i = blockIdx.x * 256 + threadIdx.x;     // float2 index, LATENT*HID/2
    float2 v = reinterpret_cast<const float2*>(W)[i];
    __nv_bfloat16 h0, l0, h1, l1;
    bfsplit(v.x, h0, l0); bfsplit(v.y, h1, l1);
    __nv_bfloat162 hh = __halves2bfloat162(h0, h1);
    __nv_bfloat162 ll = __halves2bfloat162(l0, l1);
    __nv_bfloat162* p = reinterpret_cast<__nv_bfloat162*>(o);
    const int half = LATENT * HID / 2;
    p[i] = hh; p[i + half] = hh; p[i + 2 * half] = ll;
}

// W_e1 halves summed -> w2 [1536,512] = [hi | hi | lo]
__global__ __launch_bounds__(256)
void prep_w2(const float* __restrict__ W, __nv_bfloat16* __restrict__ o)
{
    int i = blockIdx.x * 256 + threadIdx.x;     // float2 index, HID*HID/2
    float2 a = reinterpret_cast<const float2*>(W)[i];
    float2 b = reinterpret_cast<const float2*>(W + (size_t)HID * HID)[i];
    float s0 = a.x + b.x, s1 = a.y + b.y;
    __nv_bfloat16 h0, l0, h1, l1;
    bfsplit(s0, h0, l0); bfsplit(s1, h1, l1);
    __nv_bfloat162 hh = __halves2bfloat162(h0, h1);
    __nv_bfloat162 ll = __halves2bfloat162(l0, l1);
    __nv_bfloat162* p = reinterpret_cast<__nv_bfloat162*>(o);
    const int half = HID * HID / 2;
    p[i] = hh; p[i + half] = hh; p[i + 2 * half] = ll;
}

// ---------------- HMMA GEMM --------------------------------------------------
// D[64,64] tile of relu(A[M,Keff] @ B[Keff,512] + bias).
// A: [m][k] k-contig bf16;  B: [k][n] n-contig bf16 (trans-ldmatrix -> col-major).
// !P_EPI: store fp32 x to Cf[M,512] and bf16 split [hi|lo|hi] to Cx[M,1536].
//  P_EPI: gp[row] += dot(x_rowseg, We2_seg)  (atomicAdd).
static constexpr int AROW = 40;   // 32 bf16 + 8 pad = 80B (ldmatrix conflict-free)
static constexpr int BROW = 72;   // 64 bf16 + 8 pad = 144B

template<bool P_EPI>
__global__ __launch_bounds__(256)
void mma_gemm(const __nv_bfloat16* __restrict__ A,
              const __nv_bfloat16* __restrict__ B,
              const float* __restrict__ bias,
              float* __restrict__ Cf,
              __nv_bfloat16* __restrict__ Cx,
              const float* __restrict__ We2,
              float* __restrict__ gp,
              int M, int Keff)
{
    __shared__ __align__(16) __nv_bfloat16 Asm[2][64 * AROW];
    __shared__ __align__(16) __nv_bfloat16 Bsm[2][32 * BROW];

    const int tid = threadIdx.x;
    const int wid = tid >> 5, lane = tid & 31;
    const int rowBase = blockIdx.y * 64;
    const int colBase = blockIdx.x * 64;
    const int wm = wid & 3, wn = wid >> 2;   // warp -> 16 rows x 32 cols

    // tile loaders: 16B per thread for A (64x32) and B (32x64)
    const int arow = tid >> 2, aseg = tid & 3;
    const int brow = tid >> 3, bseg = tid & 7;
    const bool mok = (rowBase + arow) < M;
    const __nv_bfloat16* Ag = A + (size_t)(rowBase + arow) * Keff + aseg * 8;
    const __nv_bfloat16* Bg = B + (size_t)brow * HID + colBase + bseg * 8;

    float acc[4][4] = {};

    // stage 0
    uint4 av = make_uint4(0, 0, 0, 0);
    if (mok) av = *reinterpret_cast<const uint4*>(Ag);
    uint4 bv = *reinterpret_cast<const uint4*>(Bg);
    *reinterpret_cast<uint4*>(&Asm[0][arow * AROW + aseg * 8]) = av;
    *reinterpret_cast<uint4*>(&Bsm[0][brow * BROW + bseg * 8]) = bv;
    __syncthreads();

    // per-lane ldmatrix address components (j = lane/8 selects sub-matrix)
    const int lj = lane >> 3, lr = lane & 7;
    const int a_r = wm * 16 + (lj & 1) * 8 + lr;    // A: (m0,k0),(m8,k0),(m0,k8),(m8,k8)
    const int a_c = (lj >> 1) * 8;
    const int b_k = (lj & 1) * 8 + lr;              // B: (k0,n0),(k8,n0),(k0,n8),(k8,n8)
    const int b_n = wn * 32 + (lj >> 1) * 8;

    const int nk = Keff >> 5;                       // BK = 32
    for (int t = 0; t < nk; t++) {
        const int buf = t & 1;

        if (t + 1 < nk) {
            av = make_uint4(0, 0, 0, 0);
            if (mok) av = *reinterpret_cast<const uint4*>(Ag + (size_t)(t + 1) * 32);
            bv = *reinterpret_cast<const uint4*>(Bg + (size_t)((t + 1) * 32) * HID);
        }

        const uint32_t abase = smem_u32(&Asm[buf][0]);
        const uint32_t bbase = smem_u32(&Bsm[buf][0]);
        #pragma unroll
        for (int kh = 0; kh < 2; kh++) {            // two k16 steps per BK32
            uint32_t af[4], bf0[4], bf1[4];
            ldm_x4  (af,  abase + (uint32_t)((a_r * AROW + a_c + kh * 16) * 2));
            ldm_x4_t(bf0, bbase + (uint32_t)(((b_k + kh * 16) * BROW + b_n) * 2));
            ldm_x4_t(bf1, bbase + (uint32_t)(((b_k + kh * 16) * BROW + b_n + 16) * 2));
            mma16816(acc[0], af, bf0 + 0);
            mma16816(acc[1], af, bf0 + 2);
            mma16816(acc[2], af, bf1 + 0);
            mma16816(acc[3], af, bf1 + 2);
        }

        if (t + 1 < nk) {
            const int nb = buf ^ 1;
            *reinterpret_cast<uint4*>(&Asm[nb][arow * AROW + aseg * 8]) = av;
            *reinterpret_cast<uint4*>(&Bsm[nb][brow * BROW + bseg * 8]) = bv;
        }
        __syncthreads();
    }

    // epilogue: c fragment -> rows (l/4, l/4+8), cols (l%4)*2 per n-tile
    const int l4 = lane >> 2;
    const int l2 = (lane & 3) * 2;
    const int m_lo = rowBase + wm * 16 + l4;
    const int m_hi = m_lo + 8;
    float ps_lo = 0.f, ps_hi = 0.f;

    #pragma unroll
    for (int nt = 0; nt < 4; nt++) {
        const int cg = colBase + wn * 32 + nt * 8 + l2;
        const float b0 = bias[cg], b1 = bias[cg + 1];
        const float x0 = fmaxf(acc[nt][0] + b0, 0.f);
        const float x1 = fmaxf(acc[nt][1] + b1, 0.f);
        const float x2 = fmaxf(acc[nt][2] + b0, 0.f);
        const float x3 = fmaxf(acc[nt][3] + b1, 0.f);
        if (!P_EPI) {
            if (m_lo < M) {
                *reinterpret_cast<float2*>(Cf + (size_t)m_lo * HID + cg) = make_float2(x0, x1);
                __nv_bfloat16 h0, l0, h1, l1;
                bfsplit(x0, h0, l0); bfsplit(x1, h1, l1);
                __nv_bfloat16* p = Cx + (size_t)m_lo * K2E + cg;
                *reinterpret_cast<__nv_bfloat162*>(p)           = __halves2bfloat162(h0, h1);
                *reinterpret_cast<__nv_bfloat162*>(p + HID)     = __halves2bfloat162(l0, l1);
                *reinterpret_cast<__nv_bfloat162*>(p + 2 * HID) = __halves2bfloat162(h0, h1);
            }
            if (m_hi < M) {
                *reinterpret_cast<float2*>(Cf + (size_t)m_hi * HID + cg) = make_float2(x2, x3);
                __nv_bfloat16 h0, l0, h1, l1;
                bfsplit(x2, h0, l0); bfsplit(x3, h1, l1);
                __nv_bfloat16* p = Cx + (size_t)m_hi * K2E + cg;
                *reinterpret_cast<__nv_bfloat162*>(p)           = __halves2bfloat162(h0, h1);
                *reinterpret_cast<__nv_bfloat162*>(p + HID)     = __halves2bfloat162(l0, l1);
                *reinterpret_cast<__nv_bfloat162*>(p + 2 * HID) = __halves2bfloat162(h0, h1);
            }
        } else {
            const float w0 = We2[cg], w1 = We2[cg + 1];
            ps_lo = fmaf(x0, w0, fmaf(x1, w1, ps_lo));
            ps_hi = fmaf(x2, w0, fmaf(x3, w1, ps_hi));
        }
    }

    if (P_EPI) {
        ps_lo += __shfl_down_sync(0xffffffffu, ps_lo, 2, 4);
        ps_lo += __shfl_down_sync(0xffffffffu, ps_lo, 1, 4);
        ps_hi += __shfl_down_sync(0xffffffffu, ps_hi, 2, 4);
        ps_hi += __shfl_down_sync(0xffffffffu, ps_hi, 1, 4);
        if ((lane & 3) == 0) {
            if (m_lo < M) atomicAdd(&gp[m_lo], ps_lo);
            if (m_hi < M) atomicAdd(&gp[m_hi], ps_hi);
        }
    }
}

// ---------------- finalize (R14-proven, balanced grid (Bsz,5)) ---------------
__global__ __launch_bounds__(256)
void finalize_kernel(const float* __restrict__ g_h_p,
                     const float* __restrict__ gp,
                     const float* __restrict__ W_node,
                     const float* __restrict__ b_node,
                     const float* __restrict__ b_e2,
                     float* __restrict__ out,
                     int Bsz, int N, int has_edges)
{
    const int b = blockIdx.x;
    const int tid = threadIdx.x;
    const int warp = tid >> 5, lane = tid & 31;

    if (blockIdx.y == 0) {
        __shared__ float sh_h[HID];
        __shared__ float sh_logits[NT];
        __shared__ float sacc[8][4][4];

        {
            const float2* hp = reinterpret_cast<const float2*>(g_h_p + (size_t)b * HID);
            reinterpret_cast<float2*>(sh_h)[tid] = hp[tid];
        }
        __syncthreads();

        const float4* W4 = reinterpret_cast<const float4*>(W_node);
        float a0 = 0.f, a1 = 0.f, a2 = 0.f, a3 = 0.f;
        #pragma unroll
        for (int i = 0; i < (HID * NT / 4) / 256; i++) {
            int j = tid + i * 256;
            float hv = sh_h[j >> 2];
            float4 w = W4[j];
            a0 = fmaf(hv, w.x, a0);
            a1 = fmaf(hv, w.y, a1);
            a2 = fmaf(hv, w.z, a2);
            a3 = fmaf(hv, w.w, a3);
        }
        #pragma unroll
        for (int off = 16; off >= 4; off >>= 1) {
            a0 += __shfl_down_sync(0xffffffffu, a0, off);
            a1 += __shfl_down_sync(0xffffffffu, a1, off);
            a2 += __shfl_down_sync(0xffffffffu, a2, off);
            a3 += __shfl_down_sync(0xffffffffu, a3, off);
        }
        if (lane < 4) {
            sacc[warp][lane][0] = a0;
            sacc[warp][lane][1] = a1;
            sacc[warp][lane][2] = a2;
            sacc[warp][lane][3] = a3;
        }
        __syncthreads();
        if (tid < NT) {
            float s = 0.f;
            #pragma unroll
            for (int w = 0; w < 8; w++)
                s += sacc[w][tid >> 2][tid & 3];
            sh_logits[tid] = s + b_node[tid];
        }
        __syncthreads();

        size_t base1 = (size_t)b * N * NT;
        if (((N * NT) & 3) == 0) {
            float4 myv = *reinterpret_cast<const float4*>(&sh_logits[(tid & 3) << 2]);
            float4* o4 = reinterpret_cast<float4*>(out + base1);
            int n4 = (N * NT) >> 2;
            for (int i = tid; i < n4; i += 256)
                o4[i] = myv;
        } else {
            for (int i = tid; i < N * NT; i += 256)
                out[base1 + i] = sh_logits[i & (NT - 1)];
        }
        return;
    }

    if (!has_edges) return;
    const int s = blockIdx.y - 1;
    const float p = 1.f / (1.f + expf(-(gp[b] + b_e2[0])));
    size_t base2 = (size_t)Bsz * N * NT + (size_t)b * N * N;

    if (N == 128) {
        const int j0 = lane << 2;
        const int i0 = s * 32 + warp;
        float4* rowp = reinterpret_cast<float4*>(out + base2)
                       + (size_t)i0 * 32 + lane;
        #pragma unroll
        for (int r = 0; r < 4; r++) {
            const int i = i0 + (r << 3);
            const int d = i - j0;
            float4 v;
            v.x = (d > 0) ? p : 0.f;
            v.y = (d > 1) ? p : 0.f;
            v.z = (d > 2) ? p : 0.f;
            v.w = (d > 3) ? p : 0.f;
            *rowp = v;
            rowp += 8 * 32;
        }
    } else if ((N & 3) == 0) {
        float4* e4 = reinterpret_cast<float4*>(out + base2);
        const int nr4 = N >> 2;
        const int i0 = (s * N) >> 2, i1 = ((s + 1) * N) >> 2;
        for (int i = i0 + warp; i < i1; i += 8) {
            float4* row = e4 + (size_t)i * nr4;
            for (int c = lane; c < nr4; c += 32) {
                int j0 = c << 2;
                float4 v;
                v.x = (j0 + 0 < i) ? p : 0.f;
                v.y = (j0 + 1 < i) ? p : 0.f;
                v.z = (j0 + 2 < i) ? p : 0.f;
                v.w = (j0 + 3 < i) ? p : 0.f;
                row[c] = v;
            }
        }
    } else {
        const int i0 = (s * N) >> 2, i1 = ((s + 1) * N) >> 2;
        for (int i = i0 + warp; i < i1; i += 8) {
            float* row = out + base2 + (size_t)i * N;
            for (int j = lane; j < N; j += 32)
                row[j] = (j < i) ? p : 0.f;
        }
    }
}

// ---------------------------------------------------------------------------
// Inputs (metadata order): z, num_nodes, W_z, b_z, W_node, b_node,
//                          W_e1, b_e1, W_e2, b_e2
// num_nodes sits in device memory; derive N on host from out_size.
// ---------------------------------------------------------------------------
extern "C" void kernel_launch(void* const* d_in, const int* in_sizes, int n_in,
                              void* d_out, int out_size)
{
    const float* z      = (const float*)d_in[0];
    const float* W_z    = (const float*)d_in[2];
    const float* b_z    = (const float*)d_in[3];
    const float* W_node = (const float*)d_in[4];
    const float* b_node = (const float*)d_in[5];
    const float* W_e1   = (const float*)d_in[6];
    const float* b_e1   = (const float*)d_in[7];
    const float* W_e2   = (const float*)d_in[8];
    const float* b_e2   = (const float*)d_in[9];
    float* out = (float*)d_out;

    int Bsz = in_sizes[0] / LATENT;
    long per = (long)out_size / (long)Bsz;

    double disc = (double)NT * NT + 4.0 * (double)per;
    int N = (int)((-(double)NT + sqrt(disc)) * 0.5 + 0.5);
    int has_edges = 1;
    if ((long)N * N + (long)NT * N != per) {
        N = (int)(per / NT);
        has_edges = 0;
    }

    float *gh = nullptr, *gpp = nullptr;
    __nv_bfloat16 *zx = nullptr, *hx = nullptr, *w1 = nullptr, *w2 = nullptr;
    cudaGetSymbolAddress((void**)&gh,  g_h);
    cudaGetSymbolAddress((void**)&gpp, g_p);
    cudaGetSymbolAddress((void**)&zx,  g_zx);
    cudaGetSymbolAddress((void**)&hx,  g_hx);
    cudaGetSymbolAddress((void**)&w1,  g_w1);
    cudaGetSymbolAddress((void**)&w2,  g_w2);

    // operand prep (bf16 hi/lo split, K-extended); prep_z also zeroes g_p
    prep_z <<<(Bsz * (LATENT / 2) + 255) / 256, 256>>>(z, zx, gpp, Bsz);
    prep_w1<<<(LATENT * HID / 2) / 256, 256>>>(W_z, w1);
    prep_w2<<<(HID * HID / 2) / 256, 256>>>(W_e1, w2);

    dim3 g(HID / 64, (Bsz + 63) / 64);
    // h = relu(z @ W_z + b_z): fp32 -> g_h, bf16 split -> g_hx
    mma_gemm<false><<<g, 256>>>(zx, w1, b_z, gh, hx, nullptr, nullptr, Bsz, K1E);
    // x = relu(h @ W_e1_sum + b_e1); gp[b] += x . W_e2
    mma_gemm<true><<<g, 256>>>(hx, w2, b_e1, nullptr, nullptr, W_e2, gpp, Bsz, K2E);

    // logits + p + broadcast writes (balanced small blocks)
    dim3 fgrid(Bsz, 5);
    finalize_kernel<<<fgrid, 256>>>(gh, gpp, W_node, b_node, b_e2,
                                    out, Bsz, N, has_edges);
}

// round 16
// speedup vs baseline: 1.2690x; 1.2690x over previous
#include <cuda_runtime.h>
#include <cuda_bf16.h>
#include <math.h>
#include <stdint.h>

#define LATENT 256
#define HID 512
#define NT 16
#define MAXB 2048
#define K1E (3 * LATENT)   // 768
#define K2E (3 * HID)      // 1536

// scratch (allocation-free rule: device globals)
__device__ float g_h[MAXB * HID];
__device__ float g_p[MAXB];
__device__ float g_part[4][MAXB * HID];
__device__ __nv_bfloat16 g_zx[MAXB * K1E];
__device__ __nv_bfloat16 g_hx[(size_t)MAXB * K2E];
__device__ __nv_bfloat16 g_w1[K1E * HID];   // [kE][n], blocks [hi|hi|lo]
__device__ __nv_bfloat16 g_w2[K2E * HID];

// ---------------- helpers ---------------------------------------------------
__device__ __forceinline__ uint32_t smem_u32(const void* p) {
    uint32_t a;
    asm("{ .reg .u64 t; cvta.to.shared.u64 t, %1; cvt.u32.u64 %0, t; }"
        : "=r"(a) : "l"(p));
    return a;
}
__device__ __forceinline__ void ldm_x4(uint32_t* r, uint32_t addr) {
    asm volatile("ldmatrix.sync.aligned.m8n8.x4.shared.b16 {%0,%1,%2,%3}, [%4];"
        : "=r"(r[0]), "=r"(r[1]), "=r"(r[2]), "=r"(r[3]) : "r"(addr));
}
__device__ __forceinline__ void ldm_x4_t(uint32_t* r, uint32_t addr) {
    asm volatile("ldmatrix.sync.aligned.m8n8.x4.trans.shared.b16 {%0,%1,%2,%3}, [%4];"
        : "=r"(r[0]), "=r"(r[1]), "=r"(r[2]), "=r"(r[3]) : "r"(addr));
}
__device__ __forceinline__ void mma16816(float* c, const uint32_t* a, const uint32_t* b) {
    asm volatile(
        "mma.sync.aligned.m16n8k16.row.col.f32.bf16.bf16.f32 "
        "{%0,%1,%2,%3}, {%4,%5,%6,%7}, {%8,%9}, {%0,%1,%2,%3};"
        : "+f"(c[0]), "+f"(c[1]), "+f"(c[2]), "+f"(c[3])
        : "r"(a[0]), "r"(a[1]), "r"(a[2]), "r"(a[3]), "r"(b[0]), "r"(b[1]));
}
__device__ __forceinline__ void cp16(uint32_t dst, const void* src, bool pred) {
    int sz = pred ? 16 : 0;
    asm volatile("cp.async.cg.shared.global [%0], [%1], 16, %2;"
                 :: "r"(dst), "l"(src), "r"(sz));
}
#define CP_COMMIT() asm volatile("cp.async.commit_group;" ::: "memory")
#define CP_WAIT2()  asm volatile("cp.async.wait_group 2;" ::: "memory")
__device__ __forceinline__ void bfsplit(float x, __nv_bfloat16& hi, __nv_bfloat16& lo) {
    hi = __float2bfloat16(x);
    lo = __float2bfloat16(x - __bfloat162float(hi));
}

// ---------------- prep kernels ----------------------------------------------
// z [Bsz,256] -> zx [Bsz, 768] = [hi | lo | hi]
__global__ __launch_bounds__(256)
void prep_z(const float* __restrict__ z, __nv_bfloat16* __restrict__ zx, int Bsz)
{
    int i = blockIdx.x * 256 + threadIdx.x;     // float2 index
    if (i >= Bsz * (LATENT / 2)) return;
    int row = i / (LATENT / 2), k2 = i - row * (LATENT / 2);
    float2 v = reinterpret_cast<const float2*>(z)[i];
    __nv_bfloat16 h0, l0, h1, l1;
    bfsplit(v.x, h0, l0); bfsplit(v.y, h1, l1);
    __nv_bfloat16* o = zx + (size_t)row * K1E + k2 * 2;
    *reinterpret_cast<__nv_bfloat162*>(o)              = __halves2bfloat162(h0, h1);
    *reinterpret_cast<__nv_bfloat162*>(o + LATENT)     = __halves2bfloat162(l0, l1);
    *reinterpret_cast<__nv_bfloat162*>(o + 2 * LATENT) = __halves2bfloat162(h0, h1);
}

// W_z [256,512] -> w1 [768,512] = row-blocks [hi | hi | lo]
__global__ __launch_bounds__(256)
void prep_w1(const float* __restrict__ W, __nv_bfloat16* __restrict__ o)
{
    int i = blockIdx.x * 256 + threadIdx.x;     // float2 index, LATENT*HID/2
    float2 v = reinterpret_cast<const float2*>(W)[i];
    __nv_bfloat16 h0, l0, h1, l1;
    bfsplit(v.x, h0, l0); bfsplit(v.y, h1, l1);
    __nv_bfloat162 hh = __halves2bfloat162(h0, h1);
    __nv_bfloat162 ll = __halves2bfloat162(l0, l1);
    __nv_bfloat162* p = reinterpret_cast<__nv_bfloat162*>(o);
    const int half = LATENT * HID / 2;
    p[i] = hh; p[i + half] = hh; p[i + 2 * half] = ll;
}

// W_e1 halves summed -> w2 [1536,512] = [hi | hi | lo]
__global__ __launch_bounds__(256)
void prep_w2(const float* __restrict__ W, __nv_bfloat16* __restrict__ o)
{
    int i = blockIdx.x * 256 + threadIdx.x;     // float2 index, HID*HID/2
    float2 a = reinterpret_cast<const float2*>(W)[i];
    float2 b = reinterpret_cast<const float2*>(W + (size_t)HID * HID)[i];
    float s0 = a.x + b.x, s1 = a.y + b.y;
    __nv_bfloat16 h0, l0, h1, l1;
    bfsplit(s0, h0, l0); bfsplit(s1, h1, l1);
    __nv_bfloat162 hh = __halves2bfloat162(h0, h1);
    __nv_bfloat162 ll = __halves2bfloat162(l0, l1);
    __nv_bfloat162* p = reinterpret_cast<__nv_bfloat162*>(o);
    const int half = HID * HID / 2;
    p[i] = hh; p[i + half] = hh; p[i + 2 * half] = ll;
}

// ---------------- HMMA split-K partial GEMM ----------------------------------
// Cpart[z][M,512] = A[:, kOff:kOff+kLen] @ B[kOff:kOff+kLen, :]  (raw fp32)
// 64x64 tile, 8 warps (16x32 each), BK=32, 4-stage cp.async pipeline.
static constexpr int AROW = 40;   // 32 bf16 + 8 pad (80B rows)
static constexpr int BROW = 72;   // 64 bf16 + 8 pad (144B rows)
static constexpr int STAGES = 4;

__global__ __launch_bounds__(256)
void mma_part(const __nv_bfloat16* __restrict__ A, int lda,
              const __nv_bfloat16* __restrict__ B,
              float* __restrict__ Cpart,
              int M, int kLen)
{
    __shared__ __align__(16) __nv_bfloat16 Asm[STAGES][64 * AROW];
    __shared__ __align__(16) __nv_bfloat16 Bsm[STAGES][32 * BROW];

    const int tid = threadIdx.x;
    const int wid = tid >> 5, lane = tid & 31;
    const int rowBase = blockIdx.y * 64;
    const int colBase = blockIdx.x * 64;
    const int kOff = blockIdx.z * kLen;
    float* C = Cpart + (size_t)blockIdx.z * MAXB * HID;
    const int wm = wid & 3, wn = wid >> 2;

    // loaders: 16B/thread for A (64x32) and B (32x64)
    const int arow = tid >> 2, aseg = tid & 3;
    const int brow = tid >> 3, bseg = tid & 7;
    const bool mok = (rowBase + arow) < M;
    const __nv_bfloat16* Ag = A + (size_t)(rowBase + arow) * lda + kOff + aseg * 8;
    const __nv_bfloat16* Bg = B + (size_t)(kOff + brow) * HID + colBase + bseg * 8;

    const uint32_t a_dst0 = smem_u32(&Asm[0][arow * AROW + aseg * 8]);
    const uint32_t b_dst0 = smem_u32(&Bsm[0][brow * BROW + bseg * 8]);
    const uint32_t ASTB = 64 * AROW * 2;   // bytes per A stage
    const uint32_t BSTB = 32 * BROW * 2;

    const int nk = kLen >> 5;

    // prologue: fill STAGES-1 stages
    #pragma unroll
    for (int s = 0; s < STAGES - 1; s++) {
        if (s < nk) {
            cp16(a_dst0 + s * ASTB, Ag + (size_t)s * 32, mok);
            cp16(b_dst0 + s * BSTB, Bg + (size_t)(s * 32) * HID, true);
        }
        CP_COMMIT();
    }

    float acc[4][4] = {};

    // per-lane ldmatrix address components
    const int lj = lane >> 3, lr = lane & 7;
    const int a_r = wm * 16 + (lj & 1) * 8 + lr;
    const int a_c = (lj >> 1) * 8;
    const int b_k = (lj & 1) * 8 + lr;
    const int b_n = wn * 32 + (lj >> 1) * 8;
    const uint32_t a_lm0 = smem_u32(&Asm[0][a_r * AROW + a_c]);
    const uint32_t b_lm0 = smem_u32(&Bsm[0][b_k * BROW + b_n]);

    for (int t = 0; t < nk; t++) {
        CP_WAIT2();
        __syncthreads();

        const int buf = t & (STAGES - 1);
        const uint32_t al = a_lm0 + buf * ASTB;
        const uint32_t bl = b_lm0 + buf * BSTB;
        #pragma unroll
        for (int kh = 0; kh < 2; kh++) {
            uint32_t af[4], bf0[4], bf1[4];
            ldm_x4  (af,  al + (uint32_t)(kh * 16 * 2));
            ldm_x4_t(bf0, bl + (uint32_t)(kh * 16 * BROW * 2));
            ldm_x4_t(bf1, bl + (uint32_t)((kh * 16 * BROW + 16) * 2));
            mma16816(acc[0], af, bf0 + 0);
            mma16816(acc[1], af, bf0 + 2);
            mma16816(acc[2], af, bf1 + 0);
            mma16816(acc[3], af, bf1 + 2);
        }

        const int tn = t + STAGES - 1;
        if (tn < nk) {
            const int nb = tn & (STAGES - 1);
            cp16(a_dst0 + nb * ASTB, Ag + (size_t)tn * 32, mok);
            cp16(b_dst0 + nb * BSTB, Bg + (size_t)(tn * 32) * HID, true);
        }
        CP_COMMIT();
    }

    // raw fp32 partial store
    const int l4 = lane >> 2;
    const int l2 = (lane & 3) * 2;
    const int m_lo = rowBase + wm * 16 + l4;
    const int m_hi = m_lo + 8;
    #pragma unroll
    for (int nt = 0; nt < 4; nt++) {
        const int cg = colBase + wn * 32 + nt * 8 + l2;
        if (m_lo < M)
            *reinterpret_cast<float2*>(C + (size_t)m_lo * HID + cg) =
                make_float2(acc[nt][0], acc[nt][1]);
        if (m_hi < M)
            *reinterpret_cast<float2*>(C + (size_t)m_hi * HID + cg) =
                make_float2(acc[nt][2], acc[nt][3]);
    }
}

// ---------------- combine1: h = relu(p0+p1+bz); also emit bf16 split hx ------
__global__ __launch_bounds__(256)
void combine1_kernel(const float* __restrict__ p0,
                     const float* __restrict__ p1,
                     const float* __restrict__ bz,
                     float* __restrict__ h,
                     __nv_bfloat16* __restrict__ hx)
{
    int i = blockIdx.x * 256 + threadIdx.x;   // float4 index over Bsz*HID/4
    float4 a = reinterpret_cast<const float4*>(p0)[i];
    float4 b = reinterpret_cast<const float4*>(p1)[i];
    float4 c = reinterpret_cast<const float4*>(bz)[i & 127];
    float4 v;
    v.x = fmaxf(a.x + b.x + c.x, 0.f);
    v.y = fmaxf(a.y + b.y + c.y, 0.f);
    v.z = fmaxf(a.z + b.z + c.z, 0.f);
    v.w = fmaxf(a.w + b.w + c.w, 0.f);
    reinterpret_cast<float4*>(h)[i] = v;

    const int row = i >> 7, col = (i & 127) << 2;
    __nv_bfloat16 h0, l0, h1, l1, h2, l2, h3, l3;
    bfsplit(v.x, h0, l0); bfsplit(v.y, h1, l1);
    bfsplit(v.z, h2, l2); bfsplit(v.w, h3, l3);
    __nv_bfloat16* p = hx + (size_t)row * K2E + col;
    *reinterpret_cast<__nv_bfloat162*>(p)               = __halves2bfloat162(h0, h1);
    *reinterpret_cast<__nv_bfloat162*>(p + 2)           = __halves2bfloat162(h2, h3);
    *reinterpret_cast<__nv_bfloat162*>(p + HID)         = __halves2bfloat162(l0, l1);
    *reinterpret_cast<__nv_bfloat162*>(p + HID + 2)     = __halves2bfloat162(l2, l3);
    *reinterpret_cast<__nv_bfloat162*>(p + 2 * HID)     = __halves2bfloat162(h0, h1);
    *reinterpret_cast<__nv_bfloat162*>(p + 2 * HID + 2) = __halves2bfloat162(h2, h3);
}

// ---------------- combine2: gp[b] = dot(relu(Σ parts + b_e1), W_e2) ----------
__global__ __launch_bounds__(256)
void combine2_kernel(const float* __restrict__ parts,
                     const float* __restrict__ be1,
                     const float* __restrict__ we2,
                     float* __restrict__ gp, int Bsz)
{
    const int warp = threadIdx.x >> 5, lane = threadIdx.x & 31;
    const int r = blockIdx.x * 8 + warp;
    if (r >= Bsz) return;

    const float4* P0 = reinterpret_cast<const float4*>(parts + (size_t)r * HID);
    const float4* P1 = reinterpret_cast<const float4*>(parts + (size_t)MAXB * HID + (size_t)r * HID);
    const float4* P2 = reinterpret_cast<const float4*>(parts + (size_t)2 * MAXB * HID + (size_t)r * HID);
    const float4* P3 = reinterpret_cast<const float4*>(parts + (size_t)3 * MAXB * HID + (size_t)r * HID);
    const float4* B4 = reinterpret_cast<const float4*>(be1);
    const float4* W4 = reinterpret_cast<const float4*>(we2);

    float s = 0.f;
    #pragma unroll
    for (int q = 0; q < 4; q++) {
        int f = q * 32 + lane;
        float4 a = P0[f], b = P1[f], c = P2[f], d = P3[f];
        float4 bb = B4[f], w = W4[f];
        float x0 = fmaxf(a.x + b.x + c.x + d.x + bb.x, 0.f);
        float x1 = fmaxf(a.y + b.y + c.y + d.y + bb.y, 0.f);
        float x2 = fmaxf(a.z + b.z + c.z + d.z + bb.z, 0.f);
        float x3 = fmaxf(a.w + b.w + c.w + d.w + bb.w, 0.f);
        s = fmaf(x0, w.x, s);
        s = fmaf(x1, w.y, s);
        s = fmaf(x2, w.z, s);
        s = fmaf(x3, w.w, s);
    }
    #pragma unroll
    for (int off = 16; off; off >>= 1)
        s += __shfl_down_sync(0xffffffffu, s, off);
    if (lane == 0) gp[r] = s;
}

// ---------------- finalize (R14-proven, balanced grid (Bsz,5)) ---------------
__global__ __launch_bounds__(256)
void finalize_kernel(const float* __restrict__ g_h_p,
                     const float* __restrict__ gp,
                     const float* __restrict__ W_node,
                     const float* __restrict__ b_node,
                     const float* __restrict__ b_e2,
                     float* __restrict__ out,
                     int Bsz, int N, int has_edges)
{
    const int b = blockIdx.x;
    const int tid = threadIdx.x;
    const int warp = tid >> 5, lane = tid & 31;

    if (blockIdx.y == 0) {
        __shared__ float sh_h[HID];
        __shared__ float sh_logits[NT];
        __shared__ float sacc[8][4][4];

        {
            const float2* hp = reinterpret_cast<const float2*>(g_h_p + (size_t)b * HID);
            reinterpret_cast<float2*>(sh_h)[tid] = hp[tid];
        }
        __syncthreads();

        const float4* W4 = reinterpret_cast<const float4*>(W_node);
        float a0 = 0.f, a1 = 0.f, a2 = 0.f, a3 = 0.f;
        #pragma unroll
        for (int i = 0; i < (HID * NT / 4) / 256; i++) {
            int j = tid + i * 256;
            float hv = sh_h[j >> 2];
            float4 w = W4[j];
            a0 = fmaf(hv, w.x, a0);
            a1 = fmaf(hv, w.y, a1);
            a2 = fmaf(hv, w.z, a2);
            a3 = fmaf(hv, w.w, a3);
        }
        #pragma unroll
        for (int off = 16; off >= 4; off >>= 1) {
            a0 += __shfl_down_sync(0xffffffffu, a0, off);
            a1 += __shfl_down_sync(0xffffffffu, a1, off);
            a2 += __shfl_down_sync(0xffffffffu, a2, off);
            a3 += __shfl_down_sync(0xffffffffu, a3, off);
        }
        if (lane < 4) {
            sacc[warp][lane][0] = a0;
            sacc[warp][lane][1] = a1;
            sacc[warp][lane][2] = a2;
            sacc[warp][lane][3] = a3;
        }
        __syncthreads();
        if (tid < NT) {
            float s = 0.f;
            #pragma unroll
            for (int w = 0; w < 8; w++)
                s += sacc[w][tid >> 2][tid & 3];
            sh_logits[tid] = s + b_node[tid];
        }
        __syncthreads();

        size_t base1 = (size_t)b * N * NT;
        if (((N * NT) & 3) == 0) {
            float4 myv = *reinterpret_cast<const float4*>(&sh_logits[(tid & 3) << 2]);
            float4* o4 = reinterpret_cast<float4*>(out + base1);
            int n4 = (N * NT) >> 2;
            for (int i = tid; i < n4; i += 256)
                o4[i] = myv;
        } else {
            for (int i = tid; i < N * NT; i += 256)
                out[base1 + i] = sh_logits[i & (NT - 1)];
        }
        return;
    }

    if (!has_edges) return;
    const int s = blockIdx.y - 1;
    const float p = 1.f / (1.f + expf(-(gp[b] + b_e2[0])));
    size_t base2 = (size_t)Bsz * N * NT + (size_t)b * N * N;

    if (N == 128) {
        const int j0 = lane << 2;
        const int i0 = s * 32 + warp;
        float4* rowp = reinterpret_cast<float4*>(out + base2)
                       + (size_t)i0 * 32 + lane;
        #pragma unroll
        for (int r = 0; r < 4; r++) {
            const int i = i0 + (r << 3);
            const int d = i - j0;
            float4 v;
            v.x = (d > 0) ? p : 0.f;
            v.y = (d > 1) ? p : 0.f;
            v.z = (d > 2) ? p : 0.f;
            v.w = (d > 3) ? p : 0.f;
            *rowp = v;
            rowp += 8 * 32;
        }
    } else if ((N & 3) == 0) {
        float4* e4 = reinterpret_cast<float4*>(out + base2);
        const int nr4 = N >> 2;
        const int i0 = (s * N) >> 2, i1 = ((s + 1) * N) >> 2;
        for (int i = i0 + warp; i < i1; i += 8) {
            float4* row = e4 + (size_t)i * nr4;
            for (int c = lane; c < nr4; c += 32) {
                int j0 = c << 2;
                float4 v;
                v.x = (j0 + 0 < i) ? p : 0.f;
                v.y = (j0 + 1 < i) ? p : 0.f;
                v.z = (j0 + 2 < i) ? p : 0.f;
                v.w = (j0 + 3 < i) ? p : 0.f;
                row[c] = v;
            }
        }
    } else {
        const int i0 = (s * N) >> 2, i1 = ((s + 1) * N) >> 2;
        for (int i = i0 + warp; i < i1; i += 8) {
            float* row = out + base2 + (size_t)i * N;
            for (int j = lane; j < N; j += 32)
                row[j] = (j < i) ? p : 0.f;
        }
    }
}

// ---------------------------------------------------------------------------
// Inputs (metadata order): z, num_nodes, W_z, b_z, W_node, b_node,
//                          W_e1, b_e1, W_e2, b_e2
// num_nodes sits in device memory; derive N on host from out_size.
// ---------------------------------------------------------------------------
extern "C" void kernel_launch(void* const* d_in, const int* in_sizes, int n_in,
                              void* d_out, int out_size)
{
    const float* z      = (const float*)d_in[0];
    const float* W_z    = (const float*)d_in[2];
    const float* b_z    = (const float*)d_in[3];
    const float* W_node = (const float*)d_in[4];
    const float* b_node = (const float*)d_in[5];
    const float* W_e1   = (const float*)d_in[6];
    const float* b_e1   = (const float*)d_in[7];
    const float* W_e2   = (const float*)d_in[8];
    const float* b_e2   = (const float*)d_in[9];
    float* out = (float*)d_out;

    int Bsz = in_sizes[0] / LATENT;
    long per = (long)out_size / (long)Bsz;

    double disc = (double)NT * NT + 4.0 * (double)per;
    int N = (int)((-(double)NT + sqrt(disc)) * 0.5 + 0.5);
    int has_edges = 1;
    if ((long)N * N + (long)NT * N != per) {
        N = (int)(per / NT);
        has_edges = 0;
    }

    float *gh = nullptr, *gpp = nullptr, *gpart = nullptr;
    __nv_bfloat16 *zx = nullptr, *hx = nullptr, *w1 = nullptr, *w2 = nullptr;
    cudaGetSymbolAddress((void**)&gh,    g_h);
    cudaGetSymbolAddress((void**)&gpp,   g_p);
    cudaGetSymbolAddress((void**)&gpart, g_part);
    cudaGetSymbolAddress((void**)&zx,    g_zx);
    cudaGetSymbolAddress((void**)&hx,    g_hx);
    cudaGetSymbolAddress((void**)&w1,    g_w1);
    cudaGetSymbolAddress((void**)&w2,    g_w2);

    // operand prep (bf16 hi/lo split, K-extended)
    prep_z <<<(Bsz * (LATENT / 2) + 255) / 256, 256>>>(z, zx, Bsz);
    prep_w1<<<(LATENT * HID / 2) / 256, 256>>>(W_z, w1);
    prep_w2<<<(HID * HID / 2) / 256, 256>>>(W_e1, w2);

    // gemm1 split-K2: partials of zx @ w1
    dim3 g1(HID / 64, (Bsz + 63) / 64, 2);
    mma_part<<<g1, 256>>>(zx, K1E, w1, gpart, Bsz, K1E / 2);

    // h = relu(p0 + p1 + b_z); also bf16 split -> hx
    combine1_kernel<<<(Bsz * HID / 4) / 256, 256>>>(
        gpart, gpart + (size_t)MAXB * HID, b_z, gh, hx);

    // gemm2 split-K4: partials of hx @ w2
    dim3 g2(HID / 64, (Bsz + 63) / 64, 4);
    mma_part<<<g2, 256>>>(hx, K2E, w2, gpart, Bsz, K2E / 4);

    // gp[b] = dot(relu(Σ parts + b_e1), W_e2)
    combine2_kernel<<<(Bsz + 7) / 8, 256>>>(gpart, b_e1, W_e2, gpp, Bsz);

    // logits + p + broadcast writes (balanced small blocks)
    dim3 fgrid(Bsz, 5);
    finalize_kernel<<<fgrid, 256>>>(gh, gpp, W_node, b_node, b_e2,
                                    out, Bsz, N, has_edges);
}

// round 17
// speedup vs baseline: 1.3219x; 1.0417x over previous
#include <cuda_runtime.h>
#include <cuda_bf16.h>
#include <math.h>
#include <stdint.h>

#define LATENT 256
#define HID 512
#define NT 16
#define MAXB 2048
#define K1E (3 * LATENT)   // 768
#define K2E (3 * HID)      // 1536

// scratch (allocation-free rule: device globals)
__device__ float g_h[MAXB * HID];
__device__ float g_p[MAXB];
__device__ float g_part[4][MAXB * HID];
__device__ __nv_bfloat16 g_zx[MAXB * K1E];
__device__ __nv_bfloat16 g_hx[(size_t)MAXB * K2E];
__device__ __nv_bfloat16 g_w1[K1E * HID];   // [kE][n], blocks [hi|hi|lo]
__device__ __nv_bfloat16 g_w2[K2E * HID];

// ---------------- helpers ---------------------------------------------------
__device__ __forceinline__ uint32_t smem_u32(const void* p) {
    uint32_t a;
    asm("{ .reg .u64 t; cvta.to.shared.u64 t, %1; cvt.u32.u64 %0, t; }"
        : "=r"(a) : "l"(p));
    return a;
}
__device__ __forceinline__ void ldm_x4(uint32_t* r, uint32_t addr) {
    asm volatile("ldmatrix.sync.aligned.m8n8.x4.shared.b16 {%0,%1,%2,%3}, [%4];"
        : "=r"(r[0]), "=r"(r[1]), "=r"(r[2]), "=r"(r[3]) : "r"(addr));
}
__device__ __forceinline__ void ldm_x4_t(uint32_t* r, uint32_t addr) {
    asm volatile("ldmatrix.sync.aligned.m8n8.x4.trans.shared.b16 {%0,%1,%2,%3}, [%4];"
        : "=r"(r[0]), "=r"(r[1]), "=r"(r[2]), "=r"(r[3]) : "r"(addr));
}
__device__ __forceinline__ void mma16816(float* c, const uint32_t* a, const uint32_t* b) {
    asm volatile(
        "mma.sync.aligned.m16n8k16.row.col.f32.bf16.bf16.f32 "
        "{%0,%1,%2,%3}, {%4,%5,%6,%7}, {%8,%9}, {%0,%1,%2,%3};"
        : "+f"(c[0]), "+f"(c[1]), "+f"(c[2]), "+f"(c[3])
        : "r"(a[0]), "r"(a[1]), "r"(a[2]), "r"(a[3]), "r"(b[0]), "r"(b[1]));
}
__device__ __forceinline__ void cp16(uint32_t dst, const void* src, bool pred) {
    int sz = pred ? 16 : 0;
    asm volatile("cp.async.cg.shared.global [%0], [%1], 16, %2;"
                 :: "r"(dst), "l"(src), "r"(sz));
}
#define CP_COMMIT() asm volatile("cp.async.commit_group;" ::: "memory")
#define CP_WAIT1()  asm volatile("cp.async.wait_group 1;" ::: "memory")
__device__ __forceinline__ void bfsplit(float x, __nv_bfloat16& hi, __nv_bfloat16& lo) {
    hi = __float2bfloat16(x);
    lo = __float2bfloat16(x - __bfloat162float(hi));
}

// ---------------- fused prep ------------------------------------------------
// range0: z [Bsz,256] -> zx [Bsz,768] = [hi | lo | hi]
// range1: W_z [256,512] -> w1 [768,512] = [hi | hi | lo]
// range2: (W_e1 top + bottom) -> w2 [1536,512] = [hi | hi | lo]
__global__ __launch_bounds__(256)
void prep_all(const float* __restrict__ z, const float* __restrict__ Wz,
              const float* __restrict__ We1,
              __nv_bfloat16* __restrict__ zx, __nv_bfloat16* __restrict__ w1,
              __nv_bfloat16* __restrict__ w2, int Bsz)
{
    int i = blockIdx.x * 256 + threadIdx.x;
    const int n0 = Bsz * (LATENT / 2);
    const int n1 = LATENT * HID / 2;
    const int n2 = HID * HID / 2;

    if (i < n0) {
        int row = i / (LATENT / 2), k2 = i - row * (LATENT / 2);
        float2 v = reinterpret_cast<const float2*>(z)[i];
        __nv_bfloat16 h0, l0, h1, l1;
        bfsplit(v.x, h0, l0); bfsplit(v.y, h1, l1);
        __nv_bfloat16* o = zx + (size_t)row * K1E + k2 * 2;
        *reinterpret_cast<__nv_bfloat162*>(o)              = __halves2bfloat162(h0, h1);
        *reinterpret_cast<__nv_bfloat162*>(o + LATENT)     = __halves2bfloat162(l0, l1);
        *reinterpret_cast<__nv_bfloat162*>(o + 2 * LATENT) = __halves2bfloat162(h0, h1);
    } else if (i < n0 + n1) {
        int j = i - n0;
        float2 v = reinterpret_cast<const float2*>(Wz)[j];
        __nv_bfloat16 h0, l0, h1, l1;
        bfsplit(v.x, h0, l0); bfsplit(v.y, h1, l1);
        __nv_bfloat162 hh = __halves2bfloat162(h0, h1);
        __nv_bfloat162 ll = __halves2bfloat162(l0, l1);
        __nv_bfloat162* p = reinterpret_cast<__nv_bfloat162*>(w1);
        p[j] = hh; p[j + n1] = hh; p[j + 2 * n1] = ll;
    } else if (i < n0 + n1 + n2) {
        int j = i - n0 - n1;
        float2 a = reinterpret_cast<const float2*>(We1)[j];
        float2 b = reinterpret_cast<const float2*>(We1 + (size_t)HID * HID)[j];
        float s0 = a.x + b.x, s1 = a.y + b.y;
        __nv_bfloat16 h0, l0, h1, l1;
        bfsplit(s0, h0, l0); bfsplit(s1, h1, l1);
        __nv_bfloat162 hh = __halves2bfloat162(h0, h1);
        __nv_bfloat162 ll = __halves2bfloat162(l0, l1);
        __nv_bfloat162* p = reinterpret_cast<__nv_bfloat162*>(w2);
        p[j] = hh; p[j + n2] = hh; p[j + 2 * n2] = ll;
    }
}

// ---------------- HMMA split-K partial GEMM ----------------------------------
// Cpart[z][M,512] = A[:, kOff:kOff+kLen] @ B[kOff:kOff+kLen, :]  (raw fp32)
// 64x64 tile, 8 warps (16x32 each), BK=64, 3-stage cp.async pipeline
// (dynamic smem: 3 * (64*AROW + 64*BROW) bf16 = 55296 B).
static constexpr int AROW = 72;   // 64 bf16 + 8 pad (144B rows)
static constexpr int BROW = 72;
static constexpr int STAGES = 3;
static constexpr int A_ST = 64 * AROW;           // bf16 per A stage
static constexpr int B_ST = 64 * BROW;
static constexpr int MMA_SMEM = STAGES * (A_ST + B_ST) * 2;

__global__ __launch_bounds__(256)
void mma_part(const __nv_bfloat16* __restrict__ A, int lda,
              const __nv_bfloat16* __restrict__ B,
              float* __restrict__ Cpart,
              int M, int kLen)
{
    extern __shared__ __align__(16) __nv_bfloat16 sm[];
    __nv_bfloat16* Asm = sm;                       // [STAGES][A_ST]
    __nv_bfloat16* Bsm = sm + STAGES * A_ST;       // [STAGES][B_ST]

    const int tid = threadIdx.x;
    const int wid = tid >> 5, lane = tid & 31;
    const int rowBase = blockIdx.y * 64;
    const int colBase = blockIdx.x * 64;
    const int kOff = blockIdx.z * kLen;
    float* C = Cpart + (size_t)blockIdx.z * MAXB * HID;
    const int wm = wid & 3, wn = wid >> 2;

    // loaders: A 64x64 (512 chunks of 16B -> 2/thread), B 64x64 same
    const int ar0 = tid >> 3, aseg = tid & 7;      // rows ar0, ar0+32
    const bool mok0 = (rowBase + ar0) < M;
    const bool mok1 = (rowBase + ar0 + 32) < M;
    const __nv_bfloat16* Ag0 = A + (size_t)(rowBase + ar0) * lda + kOff + aseg * 8;
    const __nv_bfloat16* Ag1 = Ag0 + (size_t)32 * lda;
    const __nv_bfloat16* Bg0 = B + (size_t)(kOff + ar0) * HID + colBase + aseg * 8;
    const __nv_bfloat16* Bg1 = Bg0 + (size_t)32 * HID;

    const uint32_t a_dst0 = smem_u32(&Asm[ar0 * AROW + aseg * 8]);
    const uint32_t a_dst1 = smem_u32(&Asm[(ar0 + 32) * AROW + aseg * 8]);
    const uint32_t b_dst0 = smem_u32(&Bsm[ar0 * BROW + aseg * 8]);
    const uint32_t b_dst1 = smem_u32(&Bsm[(ar0 + 32) * BROW + aseg * 8]);
    const uint32_t ASTB = A_ST * 2;                // bytes per stage
    const uint32_t BSTB = B_ST * 2;

    const int nk = kLen >> 6;                      // BK = 64

    // prologue: fill 2 stages
    #pragma unroll
    for (int s = 0; s < STAGES - 1; s++) {
        if (s < nk) {
            cp16(a_dst0 + s * ASTB, Ag0 + (size_t)s * 64, mok0);
            cp16(a_dst1 + s * ASTB, Ag1 + (size_t)s * 64, mok1);
            cp16(b_dst0 + s * BSTB, Bg0 + (size_t)(s * 64) * HID, true);
            cp16(b_dst1 + s * BSTB, Bg1 + (size_t)(s * 64) * HID, true);
        }
        CP_COMMIT();
    }

    float acc[4][4] = {};

    // per-lane ldmatrix address components
    const int lj = lane >> 3, lr = lane & 7;
    const int a_r = wm * 16 + (lj & 1) * 8 + lr;
    const int a_c = (lj >> 1) * 8;
    const int b_k = (lj & 1) * 8 + lr;
    const int b_n = wn * 32 + (lj >> 1) * 8;
    const uint32_t a_lm0 = smem_u32(&Asm[a_r * AROW + a_c]);
    const uint32_t b_lm0 = smem_u32(&Bsm[b_k * BROW + b_n]);

    for (int t = 0; t < nk; t++) {
        CP_WAIT1();
        __syncthreads();

        int buf = t % STAGES;
        const uint32_t al = a_lm0 + buf * ASTB;
        const uint32_t bl = b_lm0 + buf * BSTB;
        #pragma unroll
        for (int kh = 0; kh < 4; kh++) {
            uint32_t af[4], bf0[4], bf1[4];
            ldm_x4  (af,  al + (uint32_t)(kh * 16 * 2));
            ldm_x4_t(bf0, bl + (uint32_t)(kh * 16 * BROW * 2));
            ldm_x4_t(bf1, bl + (uint32_t)((kh * 16 * BROW + 16) * 2));
            mma16816(acc[0], af, bf0 + 0);
            mma16816(acc[1], af, bf0 + 2);
            mma16816(acc[2], af, bf1 + 0);
            mma16816(acc[3], af, bf1 + 2);
        }

        const int tn = t + STAGES - 1;
        if (tn < nk) {
            int nb = tn % STAGES;
            cp16(a_dst0 + nb * ASTB, Ag0 + (size_t)tn * 64, mok0);
            cp16(a_dst1 + nb * ASTB, Ag1 + (size_t)tn * 64, mok1);
            cp16(b_dst0 + nb * BSTB, Bg0 + (size_t)(tn * 64) * HID, true);
            cp16(b_dst1 + nb * BSTB, Bg1 + (size_t)(tn * 64) * HID, true);
        }
        CP_COMMIT();
        __syncthreads();
    }

    // raw fp32 partial store
    const int l4 = lane >> 2;
    const int l2 = (lane & 3) * 2;
    const int m_lo = rowBase + wm * 16 + l4;
    const int m_hi = m_lo + 8;
    #pragma unroll
    for (int nt = 0; nt < 4; nt++) {
        const int cg = colBase + wn * 32 + nt * 8 + l2;
        if (m_lo < M)
            *reinterpret_cast<float2*>(C + (size_t)m_lo * HID + cg) =
                make_float2(acc[nt][0], acc[nt][1]);
        if (m_hi < M)
            *reinterpret_cast<float2*>(C + (size_t)m_hi * HID + cg) =
                make_float2(acc[nt][2], acc[nt][3]);
    }
}

// ---------------- combine1: h = relu(p0+p1+bz); also emit bf16 split hx ------
__global__ __launch_bounds__(256)
void combine1_kernel(const float* __restrict__ p0,
                     const float* __restrict__ p1,
                     const float* __restrict__ bz,
                     float* __restrict__ h,
                     __nv_bfloat16* __restrict__ hx)
{
    int i = blockIdx.x * 256 + threadIdx.x;   // float4 index over Bsz*HID/4
    float4 a = reinterpret_cast<const float4*>(p0)[i];
    float4 b = reinterpret_cast<const float4*>(p1)[i];
    float4 c = reinterpret_cast<const float4*>(bz)[i & 127];
    float4 v;
    v.x = fmaxf(a.x + b.x + c.x, 0.f);
    v.y = fmaxf(a.y + b.y + c.y, 0.f);
    v.z = fmaxf(a.z + b.z + c.z, 0.f);
    v.w = fmaxf(a.w + b.w + c.w, 0.f);
    reinterpret_cast<float4*>(h)[i] = v;

    const int row = i >> 7, col = (i & 127) << 2;
    __nv_bfloat16 h0, l0, h1, l1, h2, l2, h3, l3;
    bfsplit(v.x, h0, l0); bfsplit(v.y, h1, l1);
    bfsplit(v.z, h2, l2); bfsplit(v.w, h3, l3);
    __nv_bfloat16* p = hx + (size_t)row * K2E + col;
    *reinterpret_cast<__nv_bfloat162*>(p)               = __halves2bfloat162(h0, h1);
    *reinterpret_cast<__nv_bfloat162*>(p + 2)           = __halves2bfloat162(h2, h3);
    *reinterpret_cast<__nv_bfloat162*>(p + HID)         = __halves2bfloat162(l0, l1);
    *reinterpret_cast<__nv_bfloat162*>(p + HID + 2)     = __halves2bfloat162(l2, l3);
    *reinterpret_cast<__nv_bfloat162*>(p + 2 * HID)     = __halves2bfloat162(h0, h1);
    *reinterpret_cast<__nv_bfloat162*>(p + 2 * HID + 2) = __halves2bfloat162(h2, h3);
}

// ---------------- combine2: gp[b] = dot(relu(Σ parts + b_e1), W_e2) ----------
__global__ __launch_bounds__(256)
void combine2_kernel(const float* __restrict__ parts,
                     const float* __restrict__ be1,
                     const float* __restrict__ we2,
                     float* __restrict__ gp, int Bsz)
{
    const int warp = threadIdx.x >> 5, lane = threadIdx.x & 31;
    const int r = blockIdx.x * 8 + warp;
    if (r >= Bsz) return;

    const float4* P0 = reinterpret_cast<const float4*>(parts + (size_t)r * HID);
    const float4* P1 = reinterpret_cast<const float4*>(parts + (size_t)MAXB * HID + (size_t)r * HID);
    const float4* P2 = reinterpret_cast<const float4*>(parts + (size_t)2 * MAXB * HID + (size_t)r * HID);
    const float4* P3 = reinterpret_cast<const float4*>(parts + (size_t)3 * MAXB * HID + (size_t)r * HID);
    const float4* B4 = reinterpret_cast<const float4*>(be1);
    const float4* W4 = reinterpret_cast<const float4*>(we2);

    float s = 0.f;
    #pragma unroll
    for (int q = 0; q < 4; q++) {
        int f = q * 32 + lane;
        float4 a = P0[f], b = P1[f], c = P2[f], d = P3[f];
        float4 bb = B4[f], w = W4[f];
        float x0 = fmaxf(a.x + b.x + c.x + d.x + bb.x, 0.f);
        float x1 = fmaxf(a.y + b.y + c.y + d.y + bb.y, 0.f);
        float x2 = fmaxf(a.z + b.z + c.z + d.z + bb.z, 0.f);
        float x3 = fmaxf(a.w + b.w + c.w + d.w + bb.w, 0.f);
        s = fmaf(x0, w.x, s);
        s = fmaf(x1, w.y, s);
        s = fmaf(x2, w.z, s);
        s = fmaf(x3, w.w, s);
    }
    #pragma unroll
    for (int off = 16; off; off >>= 1)
        s += __shfl_down_sync(0xffffffffu, s, off);
    if (lane == 0) gp[r] = s;
}

// ---------------- finalize (R14-proven, balanced grid (Bsz,5)) ---------------
__global__ __launch_bounds__(256)
void finalize_kernel(const float* __restrict__ g_h_p,
                     const float* __restrict__ gp,
                     const float* __restrict__ W_node,
                     const float* __restrict__ b_node,
                     const float* __restrict__ b_e2,
                     float* __restrict__ out,
                     int Bsz, int N, int has_edges)
{
    const int b = blockIdx.x;
    const int tid = threadIdx.x;
    const int warp = tid >> 5, lane = tid & 31;

    if (blockIdx.y == 0) {
        __shared__ float sh_h[HID];
        __shared__ float sh_logits[NT];
        __shared__ float sacc[8][4][4];

        {
            const float2* hp = reinterpret_cast<const float2*>(g_h_p + (size_t)b * HID);
            reinterpret_cast<float2*>(sh_h)[tid] = hp[tid];
        }
        __syncthreads();

        const float4* W4 = reinterpret_cast<const float4*>(W_node);
        float a0 = 0.f, a1 = 0.f, a2 = 0.f, a3 = 0.f;
        #pragma unroll
        for (int i = 0; i < (HID * NT / 4) / 256; i++) {
            int j = tid + i * 256;
            float hv = sh_h[j >> 2];
            float4 w = W4[j];
            a0 = fmaf(hv, w.x, a0);
            a1 = fmaf(hv, w.y, a1);
            a2 = fmaf(hv, w.z, a2);
            a3 = fmaf(hv, w.w, a3);
        }
        #pragma unroll
        for (int off = 16; off >= 4; off >>= 1) {
            a0 += __shfl_down_sync(0xffffffffu, a0, off);
            a1 += __shfl_down_sync(0xffffffffu, a1, off);
            a2 += __shfl_down_sync(0xffffffffu, a2, off);
            a3 += __shfl_down_sync(0xffffffffu, a3, off);
        }
        if (lane < 4) {
            sacc[warp][lane][0] = a0;
            sacc[warp][lane][1] = a1;
            sacc[warp][lane][2] = a2;
            sacc[warp][lane][3] = a3;
        }
        __syncthreads();
        if (tid < NT) {
            float s = 0.f;
            #pragma unroll
            for (int w = 0; w < 8; w++)
                s += sacc[w][tid >> 2][tid & 3];
            sh_logits[tid] = s + b_node[tid];
        }
        __syncthreads();

        size_t base1 = (size_t)b * N * NT;
        if (((N * NT) & 3) == 0) {
            float4 myv = *reinterpret_cast<const float4*>(&sh_logits[(tid & 3) << 2]);
            float4* o4 = reinterpret_cast<float4*>(out + base1);
            int n4 = (N * NT) >> 2;
            for (int i = tid; i < n4; i += 256)
                o4[i] = myv;
        } else {
            for (int i = tid; i < N * NT; i += 256)
                out[base1 + i] = sh_logits[i & (NT - 1)];
        }
        return;
    }

    if (!has_edges) return;
    const int s = blockIdx.y - 1;
    const float p = 1.f / (1.f + expf(-(gp[b] + b_e2[0])));
    size_t base2 = (size_t)Bsz * N * NT + (size_t)b * N * N;

    if (N == 128) {
        const int j0 = lane << 2;
        const int i0 = s * 32 + warp;
        float4* rowp = reinterpret_cast<float4*>(out + base2)
                       + (size_t)i0 * 32 + lane;
        #pragma unroll
        for (int r = 0; r < 4; r++) {
            const int i = i0 + (r << 3);
            const int d = i - j0;
            float4 v;
            v.x = (d > 0) ? p : 0.f;
            v.y = (d > 1) ? p : 0.f;
            v.z = (d > 2) ? p : 0.f;
            v.w = (d > 3) ? p : 0.f;
            *rowp = v;
            rowp += 8 * 32;
        }
    } else if ((N & 3) == 0) {
        float4* e4 = reinterpret_cast<float4*>(out + base2);
        const int nr4 = N >> 2;
        const int i0 = (s * N) >> 2, i1 = ((s + 1) * N) >> 2;
        for (int i = i0 + warp; i < i1; i += 8) {
            float4* row = e4 + (size_t)i * nr4;
            for (int c = lane; c < nr4; c += 32) {
                int j0 = c << 2;
                float4 v;
                v.x = (j0 + 0 < i) ? p : 0.f;
                v.y = (j0 + 1 < i) ? p : 0.f;
                v.z = (j0 + 2 < i) ? p : 0.f;
                v.w = (j0 + 3 < i) ? p : 0.f;
                row[c] = v;
            }
        }
    } else {
        const int i0 = (s * N) >> 2, i1 = ((s + 1) * N) >> 2;
        for (int i = i0 + warp; i < i1; i += 8) {
            float* row = out + base2 + (size_t)i * N;
            for (int j = lane; j < N; j += 32)
                row[j] = (j < i) ? p : 0.f;
        }
    }
}

// ---------------------------------------------------------------------------
// Inputs (metadata order): z, num_nodes, W_z, b_z, W_node, b_node,
//                          W_e1, b_e1, W_e2, b_e2
// num_nodes sits in device memory; derive N on host from out_size.
// ---------------------------------------------------------------------------
extern "C" void kernel_launch(void* const* d_in, const int* in_sizes, int n_in,
                              void* d_out, int out_size)
{
    const float* z      = (const float*)d_in[0];
    const float* W_z    = (const float*)d_in[2];
    const float* b_z    = (const float*)d_in[3];
    const float* W_node = (const float*)d_in[4];
    const float* b_node = (const float*)d_in[5];
    const float* W_e1   = (const float*)d_in[6];
    const float* b_e1   = (const float*)d_in[7];
    const float* W_e2   = (const float*)d_in[8];
    const float* b_e2   = (const float*)d_in[9];
    float* out = (float*)d_out;

    int Bsz = in_sizes[0] / LATENT;
    long per = (long)out_size / (long)Bsz;

    double disc = (double)NT * NT + 4.0 * (double)per;
    int N = (int)((-(double)NT + sqrt(disc)) * 0.5 + 0.5);
    int has_edges = 1;
    if ((long)N * N + (long)NT * N != per) {
        N = (int)(per / NT);
        has_edges = 0;
    }

    float *gh = nullptr, *gpp = nullptr, *gpart = nullptr;
    __nv_bfloat16 *zx = nullptr, *hx = nullptr, *w1 = nullptr, *w2 = nullptr;
    cudaGetSymbolAddress((void**)&gh,    g_h);
    cudaGetSymbolAddress((void**)&gpp,   g_p);
    cudaGetSymbolAddress((void**)&gpart, g_part);
    cudaGetSymbolAddress((void**)&zx,    g_zx);
    cudaGetSymbolAddress((void**)&hx,    g_hx);
    cudaGetSymbolAddress((void**)&w1,    g_w1);
    cudaGetSymbolAddress((void**)&w2,    g_w2);

    static bool attr_set = false;
    if (!attr_set) {
        cudaFuncSetAttribute(mma_part,
            cudaFuncAttributeMaxDynamicSharedMemorySize, MMA_SMEM);
        attr_set = true;
    }

    // fused operand prep (bf16 hi/lo split, K-extended)
    {
        int tot = Bsz * (LATENT / 2) + LATENT * HID / 2 + HID * HID / 2;
        prep_all<<<(tot + 255) / 256, 256>>>(z, W_z, W_e1, zx, w1, w2, Bsz);
    }

    // gemm1 split-K2: partials of zx @ w1  (kLen = 384)
    dim3 g1(HID / 64, (Bsz + 63) / 64, 2);
    mma_part<<<g1, 256, MMA_SMEM>>>(zx, K1E, w1, gpart, Bsz, K1E / 2);

    // h = relu(p0 + p1 + b_z); also bf16 split -> hx
    combine1_kernel<<<(Bsz * HID / 4) / 256, 256>>>(
        gpart, gpart + (size_t)MAXB * HID, b_z, gh, hx);

    // gemm2 split-K4: partials of hx @ w2  (kLen = 384)
    dim3 g2(HID / 64, (Bsz + 63) / 64, 4);
    mma_part<<<g2, 256, MMA_SMEM>>>(hx, K2E, w2, gpart, Bsz, K2E / 4);

    // gp[b] = dot(relu(Σ parts + b_e1), W_e2)
    combine2_kernel<<<(Bsz + 7) / 8, 256>>>(gpart, b_e1, W_e2, gpp, Bsz);

    // logits + p + broadcast writes (balanced small blocks)
    dim3 fgrid(Bsz, 5);
    finalize_kernel<<<fgrid, 256>>>(gh, gpp, W_node, b_node, b_e2,
                                    out, Bsz, N, has_edges);
}